// round 14
// baseline (speedup 1.0000x reference)
#include <cuda_runtime.h>
#include <cuda_bf16.h>
#include <math.h>

#define BB 4
#define CC 64
#define NN 64
#define NCANON 2050

typedef unsigned long long ull;

// ---------------------------------------------------------------------------
// Device scratch
// ---------------------------------------------------------------------------
__device__ float2 g_G[BB * NN * 3 * CC * CC];   // 25.2 MB: G[b][v][kh][i][j]
__device__ float  g_part[BB * NN * NN];         // weighted per-frequency logdets
__device__ int    g_cnt[BB];                    // completion counters (self-resetting)

// ---------------------------------------------------------------------------
// f32x2 packed helpers
// ---------------------------------------------------------------------------
__device__ __forceinline__ ull pk2(float lo, float hi) {
    ull r; asm("mov.b64 %0, {%1,%2};" : "=l"(r) : "f"(lo), "f"(hi)); return r;
}
__device__ __forceinline__ void upk2(ull v, float &lo, float &hi) {
    asm("mov.b64 {%0,%1}, %2;" : "=f"(lo), "=f"(hi) : "l"(v));
}
__device__ __forceinline__ ull fma2(ull a, ull b, ull c) {
    ull r; asm("fma.rn.f32x2 %0, %1, %2, %3;" : "=l"(r) : "l"(a), "l"(b), "l"(c));
    return r;
}
__device__ __forceinline__ ull sel4(ull a0, ull a1, ull a2, ull a3, int s) {
    ull x01 = (s & 1) ? a1 : a0;
    ull x23 = (s & 1) ? a3 : a2;
    return (s & 2) ? x23 : x01;
}

// ---------------------------------------------------------------------------
// Kernel 1: G build
// ---------------------------------------------------------------------------
__global__ __launch_bounds__(256) void gbuild_kernel(const float* __restrict__ K) {
    int v = blockIdx.x & 63;
    int b = blockIdx.x >> 6;
    float th = -6.283185307179586f * (float)v / 64.0f;
    float s1, c1;
    sincosf(th, &s1, &c1);
    float c2 = c1 * c1 - s1 * s1;
    float s2 = 2.0f * s1 * c1;
    long long base = ((long long)(b * 64 + v)) * 3 * 4096;
    for (int e = threadIdx.x; e < 4096; e += 256) {
        int i = e >> 6, j = e & 63;
        const float* kp = K + ((size_t)(b * 64 + i) * 64 + j) * 9;
        float k[9];
#pragma unroll
        for (int t = 0; t < 9; t++) k[t] = kp[t];
        if (i == j) k[4] += 1.0f;
#pragma unroll
        for (int kh = 0; kh < 3; kh++) {
            float re = k[3 * kh] + k[3 * kh + 1] * c1 + k[3 * kh + 2] * c2;
            float im = k[3 * kh + 1] * s1 + k[3 * kh + 2] * s2;
            g_G[base + kh * 4096 + e] = make_float2(re, im);
        }
    }
}

// ---------------------------------------------------------------------------
// Kernel 2: circular conv (unchanged — known good)
// ---------------------------------------------------------------------------
__global__ __launch_bounds__(256) void conv_kernel(const float* __restrict__ x,
                                                   const float* __restrict__ K,
                                                   const float* __restrict__ bias,
                                                   float* __restrict__ out) {
    __shared__ float sIn[66 * 68];
    __shared__ float sTap[9];
    int co = blockIdx.x;
    int b  = blockIdx.y;
    int tid = threadIdx.x;
    int ty = tid >> 4, tx = tid & 15;
    int py = ty * 4, px = tx * 4;

    float acc[4][4];
#pragma unroll
    for (int r = 0; r < 4; r++)
#pragma unroll
        for (int c = 0; c < 4; c++) acc[r][c] = 0.0f;

    for (int ci = 0; ci < 64; ci++) {
        __syncthreads();
        const float* xp = x + (size_t)(b * 64 + ci) * 4096;
        for (int e = tid; e < 66 * 66; e += 256) {
            int rr = e / 66;
            int cc2 = e - rr * 66;
            int gy = (rr + 63) & 63;
            int gx = (cc2 + 63) & 63;
            sIn[rr * 68 + cc2] = xp[gy * 64 + gx];
        }
        if (tid < 9) {
            float t = K[((size_t)(b * 64 + co) * 64 + ci) * 9 + tid];
            if (ci == co && tid == 4) t += 1.0f;
            sTap[tid] = t;
        }
        __syncthreads();
        float tp[9];
#pragma unroll
        for (int t = 0; t < 9; t++) tp[t] = sTap[t];
        float patch[6][6];
#pragma unroll
        for (int dr = 0; dr < 6; dr++)
#pragma unroll
            for (int dc = 0; dc < 6; dc++)
                patch[dr][dc] = sIn[(py + dr) * 68 + px + dc];
#pragma unroll
        for (int r = 0; r < 4; r++)
#pragma unroll
            for (int c = 0; c < 4; c++) {
                float a = acc[r][c];
#pragma unroll
                for (int kh = 0; kh < 3; kh++)
#pragma unroll
                    for (int kw = 0; kw < 3; kw++)
                        a = fmaf(tp[kh * 3 + kw], patch[r + kh][c + kw], a);
                acc[r][c] = a;
            }
    }
    float bv = bias[b * 64 + co];
    float* op = out + (size_t)(b * 64 + co) * 4096;
#pragma unroll
    for (int r = 0; r < 4; r++)
#pragma unroll
        for (int c = 0; c < 4; c++)
            op[(py + r) * 64 + px + c] = acc[r][c] + bv;
}

// ---------------------------------------------------------------------------
// Kernel 3: complex 64x64 LU. 256 threads.
//   tx = tid>>4 (column group: cols 4tx..4tx+3) -> warp w owns cols 8w..8w+7
//   ty = tid&15 (row group: rows 4ty..4ty+3)
// Owner warp (k>>3) does pivot search + multipliers pre-B1 (others skip).
// Warp-uniform COLUMN retirement: warp w inactive once 8w+7 < k.
// 2 barriers/step. Fused final reduction (last CTA per sample).
// ---------------------------------------------------------------------------
struct LuS {
    ull    rowV[2][64];
    ull    rowVs[2][64];
    ull    rowK[2][64];
    ull    colM[2][64];
    ull    candKey[2];
    float  pivN2[64];
    float  red[64];
    double dred[256];
};

__global__ __launch_bounds__(256) void lu_kernel(float* __restrict__ out) {
    int b = blockIdx.y;
    int c = blockIdx.x;
    int u, v;
    float weight;
    if (c < 1984)      { u = 1 + (c >> 6); v = c & 63; weight = 2.0f; }
    else if (c < 2017) { u = 0;  v = c - 1984; weight = (v == 0 || v == 32) ? 1.0f : 2.0f; }
    else               { u = 32; v = c - 2017; weight = (v == 0 || v == 32) ? 1.0f : 2.0f; }

    int tid = threadIdx.x;
    int tx = tid >> 4;       // column group
    int ty = tid & 15;       // row group
    int w  = tid >> 5;       // warp: cols 8w..8w+7
    int lane = tid & 31;

    __shared__ union {
        float2 A[4096];
        LuS bf;
    } sm;

    // ---- build A = sum_kh G[b,v,kh] * wu^kh (coalesced), stage in smem ----
    const float2* __restrict__ Gb = g_G + (long long)((b * 64 + v) * 3) * 4096;
    float su, cu;
    sincosf(-6.283185307179586f * (float)u / 64.0f, &su, &cu);
    float cu2 = cu * cu - su * su;
    float su2 = 2.0f * su * cu;

#pragma unroll 4
    for (int e = tid; e < 4096; e += 256) {
        float2 g0 = Gb[e];
        float2 g1 = Gb[4096 + e];
        float2 g2 = Gb[8192 + e];
        float re = g0.x + cu * g1.x - su * g1.y + cu2 * g2.x - su2 * g2.y;
        float im = g0.y + cu * g1.y + su * g1.x + cu2 * g2.y + su2 * g2.x;
        sm.A[e] = make_float2(re, im);
    }
    __syncthreads();

    ull acc[4][4];
#pragma unroll
    for (int r = 0; r < 4; r++)
#pragma unroll
        for (int c2 = 0; c2 < 4; c2++) {
            float2 t = sm.A[(4 * ty + r) * 64 + 4 * tx + c2];
            acc[r][c2] = pk2(t.x, t.y);
        }
    __syncthreads();   // smem becomes LuS

    for (int k = 0; k < 64; k++) {
        int pb  = k & 1;
        int c8  = k >> 2;        // owning tx of column k
        int kc  = k & 3;         // col within tile
        int kty = k >> 2;        // owning ty of row k
        int krl = k & 3;         // row within tile
        bool act = (8 * w + 7 >= k);   // warp-uniform column guard

        // ---- S1: owner warp does pivot search + multipliers ----
        if (w == (k >> 3)) {
            ull vkr[4] = {0ull, 0ull, 0ull, 0ull};
            ull bestKey = 0ull;
            if (tx == c8) {
#pragma unroll
                for (int r = 0; r < 4; r++) {
                    vkr[r] = sel4(acc[r][0], acc[r][1], acc[r][2], acc[r][3], kc);
                    float re, im;
                    upk2(vkr[r], re, im);
                    float n2 = fmaf(re, re, im * im);
                    int i = 4 * ty + r;
                    ull key = ((ull)__float_as_uint(n2) << 32) | (ull)(64 - i);
                    if (i >= k && key > bestKey) bestKey = key;
                }
            }
#pragma unroll
            for (int off = 16; off >= 1; off >>= 1) {
                ull o = __shfl_xor_sync(0xffffffffu, bestKey, off);
                if (o > bestKey) bestKey = o;
            }
            int p = 64 - (int)(bestKey & 0xffffffffull);
            float bn = __uint_as_float((unsigned)(bestKey >> 32));
            if (lane == 0) {
                sm.bf.candKey[pb] = bestKey;
                sm.bf.pivN2[k] = bn;
            }
            int half = (c8 & 1) << 4;
            ull cpk = sel4(vkr[0], vkr[1], vkr[2], vkr[3], p & 3);
            ull apk = __shfl_sync(0xffffffffu, cpk, half | (p >> 2));
            ull ckk = sel4(vkr[0], vkr[1], vkr[2], vkr[3], krl);
            ull akk = __shfl_sync(0xffffffffu, ckk, half | kty);
            if (tx == c8) {
                float pre, pim;
                upk2(apk, pre, pim);
                float inv = __fdividef(1.0f, bn);
                float ipre = pre * inv, ipim = -pim * inv;   // 1/pivot
#pragma unroll
                for (int r = 0; r < 4; r++) {
                    int i = 4 * ty + r;
                    ull a = (i == p) ? akk : vkr[r];   // post-swap column value
                    float are, aim;
                    upk2(a, are, aim);
                    float mr = are * ipre - aim * ipim;
                    float mi = are * ipim + aim * ipre;
                    if (i <= k) { mr = 0.0f; mi = 0.0f; }
                    sm.bf.colM[pb][i] = pk2(mr, mi);
                }
            }
        }
        // row-k staging (active columns only)
        if (act && ty == kty) {
#pragma unroll
            for (int r = 0; r < 4; r++)
                if (r == krl) {
#pragma unroll
                    for (int c2 = 0; c2 < 4; c2++)
                        sm.bf.rowK[pb][4 * tx + c2] = acc[r][c2];
                }
        }
        __syncthreads();   // B1

        // ---- S2: read pivot index; row-p owners publish pivot row ----
        ull bk = sm.bf.candKey[pb];
        int p = 64 - (int)(bk & 0xffffffffull);
        if (act && ty == (p >> 2)) {
            int pl = p & 3;
#pragma unroll
            for (int r = 0; r < 4; r++)
                if (r == pl) {
#pragma unroll
                    for (int c2 = 0; c2 < 4; c2++) {
                        ull vv = acc[r][c2];
                        sm.bf.rowV[pb][4 * tx + c2] = vv;
                        float vr_, vi_;
                        upk2(vv, vr_, vi_);
                        sm.bf.rowVs[pb][4 * tx + c2] = pk2(vi_, -vr_);
                    }
                }
        }
        __syncthreads();   // B2

        // ---- S3: swaps + rank-1 update (active warps only) ----
        if (act) {
            if (ty == kty) {
#pragma unroll
                for (int r = 0; r < 4; r++)
                    if (r == krl) {
#pragma unroll
                        for (int c2 = 0; c2 < 4; c2++)
                            acc[r][c2] = sm.bf.rowV[pb][4 * tx + c2];
                    }
            }
            if (p != k && ty == (p >> 2)) {
                int pl = p & 3;
#pragma unroll
                for (int r = 0; r < 4; r++)
                    if (r == pl) {
#pragma unroll
                        for (int c2 = 0; c2 < 4; c2++)
                            acc[r][c2] = sm.bf.rowK[pb][4 * tx + c2];
                    }
            }
            ull rv[4], rs[4];
#pragma unroll
            for (int c2 = 0; c2 < 4; c2++) {
                rv[c2] = sm.bf.rowV[pb][4 * tx + c2];
                rs[c2] = sm.bf.rowVs[pb][4 * tx + c2];
            }
#pragma unroll
            for (int r = 0; r < 4; r++) {
                ull m = sm.bf.colM[pb][4 * ty + r];
                float mr, mi;
                upk2(m, mr, mi);
                ull mrd = pk2(-mr, -mr);
                ull mid = pk2(mi, mi);
#pragma unroll
                for (int c2 = 0; c2 < 4; c2++) {
                    acc[r][c2] = fma2(mrd, rv[c2], acc[r][c2]);
                    acc[r][c2] = fma2(mid, rs[c2], acc[r][c2]);
                }
            }
        }
    }

    // ---- logs + per-frequency partial ----
    __syncthreads();
    if (tid < 64) sm.bf.red[tid] = logf(sm.bf.pivN2[tid]);
    __syncthreads();
    __shared__ int s_last;
    if (tid == 0) {
        float s = 0.0f;
#pragma unroll
        for (int t = 0; t < 64; t++) s += sm.bf.red[t];
        g_part[b * 4096 + u * 64 + v] = weight * 0.5f * s;
        __threadfence();
        int old = atomicAdd(&g_cnt[b], 1);
        s_last = (old == NCANON - 1) ? 1 : 0;
    }
    __syncthreads();

    // ---- last CTA per sample: deterministic fixed-order reduction ----
    if (s_last) {
        __threadfence();
        double s = 0.0;
        for (int e = tid; e < 4096; e += 256)
            s += (double)__ldcg(&g_part[b * 4096 + e]);
        sm.bf.dred[tid] = s;
        __syncthreads();
        for (int st = 128; st > 0; st >>= 1) {
            if (tid < st) sm.bf.dred[tid] += sm.bf.dred[tid + st];
            __syncthreads();
        }
        if (tid == 0) {
            out[1048576 + b] = (float)sm.bf.dred[0];
            g_cnt[b] = 0;   // reset for next replay (deterministic)
        }
    }
}

// ---------------------------------------------------------------------------
extern "C" void kernel_launch(void* const* d_in, const int* in_sizes, int n_in,
                              void* d_out, int out_size) {
    const float* x = nullptr;
    const float* K = nullptr;
    const float* bias = nullptr;
    for (int i = 0; i < n_in; i++) {
        if (in_sizes[i] == 1048576)      x    = (const float*)d_in[i];
        else if (in_sizes[i] == 147456)  K    = (const float*)d_in[i];
        else if (in_sizes[i] == 256)     bias = (const float*)d_in[i];
    }
    float* out = (float*)d_out;

    gbuild_kernel<<<256, 256>>>(K);
    conv_kernel<<<dim3(64, 4), 256>>>(x, K, bias, out);
    lu_kernel<<<dim3(NCANON, 4), 256>>>(out);
}